// round 8
// baseline (speedup 1.0000x reference)
#include <cuda_runtime.h>
#include <math.h>

#define Hs    64
#define SEQ   2048
#define Bt    256
#define IN    32
#define GATES 256   // 4*H
#define PADH  68    // padded h row stride (floats): halves 36 floats apart
#define PADP  272   // padded sP block stride (floats)

typedef unsigned long long u64;

__device__ float g_xproj[(size_t)SEQ * Bt * GATES];   // [t][row][g], bias0 folded

__device__ __forceinline__ u64 fma2(u64 a, u64 b, u64 c) {
    u64 d;
    asm("fma.rn.f32x2 %0, %1, %2, %3;" : "=l"(d) : "l"(a), "l"(b), "l"(c));
    return d;
}
__device__ __forceinline__ u64 pk(float a, float b) {
    u64 r;
    asm("mov.b64 %0, {%1, %2};" : "=l"(r) : "f"(a), "f"(b));
    return r;
}
__device__ __forceinline__ float hsum(u64 v) {
    float a, b;
    asm("mov.b64 {%0, %1}, %2;" : "=f"(a), "=f"(b) : "l"(v));
    return a + b;
}
__device__ __forceinline__ float ex2a(float x) {
    float y; asm("ex2.approx.f32 %0, %1;" : "=f"(y) : "f"(x)); return y;
}
__device__ __forceinline__ float rcpa(float x) {
    float y; asm("rcp.approx.f32 %0, %1;" : "=f"(y) : "f"(x)); return y;
}
__device__ __forceinline__ float sigf(float x) {
    return rcpa(1.0f + ex2a(-1.4426950408889634f * x));
}
__device__ __forceinline__ float tanhfa(float x) {
    return fmaf(2.0f, sigf(2.0f * x), -1.0f);
}

// ============================================================================
// Prepass (round-4 proven version): xproj = Wih0·x + bih0 + bhh0
// 1 gate/thread, 32 weight regs -> high occupancy for this DRAM-bound kernel.
// ============================================================================
__global__ void __launch_bounds__(256)
xproj_kernel(const float* __restrict__ x,
             const float* __restrict__ Wih0,
             const float* __restrict__ bih0,
             const float* __restrict__ bhh0)
{
    __shared__ float sx[64 * IN];
    const int g   = threadIdx.x;
    const int row = blockIdx.y;
    const int t0  = blockIdx.x * 64;

    const float* xs = x + ((size_t)row * SEQ + t0) * IN;
    for (int i = g; i < 64 * IN / 4; i += 256)
        ((float4*)sx)[i] = ((const float4*)xs)[i];

    u64 w[IN / 2];
    const u64* wp = (const u64*)(Wih0 + g * IN);
#pragma unroll
    for (int k = 0; k < IN / 2; k++) w[k] = wp[k];
    const u64 bp = pk(bih0[g] + bhh0[g], 0.0f);
    __syncthreads();

    for (int tt = 0; tt < 64; tt++) {
        const ulonglong2* xv = (const ulonglong2*)(sx + tt * IN);
        u64 a = bp;
#pragma unroll
        for (int k = 0; k < IN / 4; k++) {
            ulonglong2 v = xv[k];
            a = fma2(w[2 * k],     v.x, a);
            a = fma2(w[2 * k + 1], v.y, a);
        }
        g_xproj[((size_t)(t0 + tt) * Bt + row) * GATES + g] = hsum(a);
    }
}

// ============================================================================
// Main: 128 CTAs x 512 threads. Warp w owns gates [w*16, w*16+16); lanes 0-15
// are K-half 0, lanes 16-31 K-half 1. Cross-half combine = 1 shfl_xor(16);
// activation applied in gate warps; sP holds ACTIVATED gates. Padded smem
// layouts keep every LDS/STS at 1 wavefront. 2 barriers/step.
// ============================================================================
__global__ void __launch_bounds__(512, 1)
lstm2_r8(const float* __restrict__ h0g,
         const float* __restrict__ c0g,
         const float* __restrict__ Whh0,
         const float* __restrict__ Wih1,
         const float* __restrict__ Whh1,
         const float* __restrict__ bih1,
         const float* __restrict__ bhh1,
         const float* __restrict__ Wh,
         const float* __restrict__ bhp,
         float* __restrict__ out)
{
    __shared__ float sP[4 * PADP];     // [layer*2+row] activated gates, padded
    __shared__ float sH0[2 * PADH];    // [row] padded (half1 at +36 floats)
    __shared__ float sH1[2 * PADH];
    __shared__ float sPr[8];           // [parity][4]

    const int tid  = threadIdx.x;
    const int wid  = tid >> 5;
    const int lane = tid & 31;
    const int half = lane >> 4;               // K-half
    const int g    = wid * 16 + (lane & 15);  // gate row 0..255
    const int gsel = g >> 6;                  // 0:i 1:f 2:g 3:o (warp-uniform)
    const int r0   = blockIdx.x * 2;

    // register weights: half-rows (32 floats = 16 u64 each)
    u64 wh0[16], wx1[16], wh1[16];
    {
        const u64* p0 = (const u64*)(Whh0 + g * Hs + half * 32);
        const u64* p1 = (const u64*)(Wih1 + g * Hs + half * 32);
        const u64* p2 = (const u64*)(Whh1 + g * Hs + half * 32);
#pragma unroll
        for (int k = 0; k < 16; k++) { wh0[k] = p0[k]; wx1[k] = p1[k]; wh1[k] = p2[k]; }
    }
    const float b1  = bih1[g] + bhh1[g];
    const float bh0 = bhp[0];
    const float whj = Wh[tid & 63];

    float c = 0.0f, hl = 0.0f, hn_prev = 0.0f;
    if (tid < 128) {                          // L0 updaters (warps 0-3)
        int r = tid >> 6, j = tid & 63;
        float h = h0g[(size_t)(r0 + r) * Hs + j];
        sH0[r * PADH + j + (j >> 5) * 4] = h;
        c  = c0g[(size_t)(r0 + r) * Hs + j];
        hl = h;
    }
    if (tid >= 256 && tid < 384) {            // L1 updaters (warps 8-11)
        int ub = tid - 256, r = ub >> 6, j = ub & 63;
        float h = h0g[(size_t)Bt * Hs + (size_t)(r0 + r) * Hs + j];
        sH1[r * PADH + j + (j >> 5) * 4] = h;
        c  = c0g[(size_t)Bt * Hs + (size_t)(r0 + r) * Hs + j];
        hl = h;
    }

    // xproj pointer for this thread's (row = half) lane; step stride Bt*GATES
    const size_t XSTR = (size_t)Bt * GATES;
    const float* xpp = g_xproj + (size_t)(r0 + half) * GATES + g;
    float xp = *xpp;                          // t = 0
    xpp += XSTR;                              // points at t = 1
    __syncthreads();

    const ulonglong2* H0 = (const ulonglong2*)sH0;
    const ulonglong2* H1 = (const ulonglong2*)sH1;
    const int hb0 = half * 9;                 // float4 offset of this K-half

    for (int u = 0; u <= SEQ; u++) {
        // prefetch xproj(u+1)
        float xpn = 0.0f;
        if (u + 1 < SEQ) xpn = *xpp;
        xpp += XSTR;

        // deferred head reduce for t=u-2 (hn_prev from iter u-1's L1 update)
        if (tid >= 256 && tid < 384 && u >= 2) {
            float p = hn_prev * whj;
#pragma unroll
            for (int off = 16; off; off >>= 1)
                p += __shfl_down_sync(0xffffffffu, p, off);
            if ((tid & 31) == 0) sPr[(u & 1) * 4 + ((tid >> 5) - 8)] = p;
        }

        // ---------- phase 1: gates (f32x2), K-halves in one warp ----------
        u64 A0, A1, Q0, Q1;
        if (half == 0) { A0 = pk(xp, 0.f); A1 = 0ULL; Q0 = pk(b1, 0.f); Q1 = 0ULL; }
        else           { A0 = 0ULL; A1 = pk(xp, 0.f); Q0 = 0ULL; Q1 = pk(b1, 0.f); }
#pragma unroll
        for (int k = 0; k < 8; k++) {         // h0(u-1) feeds Whh0 AND Wih1
            ulonglong2 v0 = H0[hb0 + k];
            ulonglong2 v1 = H0[17 + hb0 + k];
            A0 = fma2(wh0[2*k],   v0.x, A0);
            A0 = fma2(wh0[2*k+1], v0.y, A0);
            A1 = fma2(wh0[2*k],   v1.x, A1);
            A1 = fma2(wh0[2*k+1], v1.y, A1);
            Q0 = fma2(wx1[2*k],   v0.x, Q0);
            Q0 = fma2(wx1[2*k+1], v0.y, Q0);
            Q1 = fma2(wx1[2*k],   v1.x, Q1);
            Q1 = fma2(wx1[2*k+1], v1.y, Q1);
        }
#pragma unroll
        for (int k = 0; k < 8; k++) {         // Whh1 over h1(u-2)
            ulonglong2 v0 = H1[hb0 + k];
            ulonglong2 v1 = H1[17 + hb0 + k];
            Q0 = fma2(wh1[2*k],   v0.x, Q0);
            Q0 = fma2(wh1[2*k+1], v0.y, Q0);
            Q1 = fma2(wh1[2*k],   v1.x, Q1);
            Q1 = fma2(wh1[2*k+1], v1.y, Q1);
        }
        // combine K-halves: each half finalizes its own row's gate
        {
            float A0s = hsum(A0), A1s = hsum(A1);
            float Q0s = hsum(Q0), Q1s = hsum(Q1);
            float sendA = half ? A0s : A1s;
            float rA = __shfl_xor_sync(0xffffffffu, sendA, 16);
            float Ar = half ? (A1s + rA) : (A0s + rA);
            float sendQ = half ? Q0s : Q1s;
            float rQ = __shfl_xor_sync(0xffffffffu, sendQ, 16);
            float Qr = half ? (Q1s + rQ) : (Q0s + rQ);
            float actA = (gsel == 2) ? tanhfa(Ar) : sigf(Ar);
            float actQ = (gsel == 2) ? tanhfa(Qr) : sigf(Qr);
            if (u < SEQ) sP[half * PADP + g] = actA;        // L0 row=half
            if (u >= 1)  sP[(2 + half) * PADP + g] = actQ;  // L1 row=half
        }
        xp = xpn;
        __syncthreads();

        // ---------- phase 2: cell updates (activated gates in sP) ----------
        if (tid < 128 && u < SEQ) {           // L0: time u
            int r = tid >> 6, j = tid & 63;
            const float* p = sP + r * PADP;
            float I = p[j], F = p[64 + j], G = p[128 + j], O = p[192 + j];
            c = F * c + I * G;
            float hn = O * tanhfa(c);
            hl = hn;
            sH0[r * PADH + j + (j >> 5) * 4] = hn;
        }
        if (tid >= 256 && tid < 384 && u >= 1) {  // L1: time u-1
            int ub = tid - 256, r = ub >> 6, j = ub & 63;
            const float* p = sP + (2 + r) * PADP;
            float I = p[j], F = p[64 + j], G = p[128 + j], O = p[192 + j];
            c = F * c + I * G;
            float hn = O * tanhfa(c);
            hl = hn;
            sH1[r * PADH + j + (j >> 5) * 4] = hn;
            hn_prev = hn;                     // reduced at top of next iter
        }
        if (u >= 2 && (tid == 384 || tid == 385)) {  // head out, t=u-2
            int row = tid - 384;
            float v = sPr[(u & 1) * 4 + row * 2]
                    + sPr[(u & 1) * 4 + row * 2 + 1] + bh0;
            out[(size_t)(r0 + row) * SEQ + (u - 2)] = sigf(v);
        }
        __syncthreads();
    }

    // post-loop: reduce hn_prev (L1 t=SEQ-1) and emit last head sample
    if (tid >= 256 && tid < 384) {
        float p = hn_prev * whj;
#pragma unroll
        for (int off = 16; off; off >>= 1)
            p += __shfl_down_sync(0xffffffffu, p, off);
        if ((tid & 31) == 0) sPr[4 + ((tid >> 5) - 8)] = p;
    }
    __syncthreads();
    if (tid == 384 || tid == 385) {
        int row = tid - 384;
        float v = sPr[4 + row * 2] + sPr[4 + row * 2 + 1] + bh0;
        out[(size_t)(r0 + row) * SEQ + (SEQ - 1)] = sigf(v);
    }

    // final h, c (from updater registers)
    const size_t hbo = (size_t)Bt * SEQ;
    const size_t cbo = hbo + 2 * (size_t)Bt * Hs;
    if (tid < 128) {
        int r = tid >> 6, j = tid & 63;
        out[hbo + (size_t)(r0 + r) * Hs + j] = hl;
        out[cbo + (size_t)(r0 + r) * Hs + j] = c;
    }
    if (tid >= 256 && tid < 384) {
        int ub = tid - 256, r = ub >> 6, j = ub & 63;
        out[hbo + Bt * Hs + (size_t)(r0 + r) * Hs + j] = hl;
        out[cbo + Bt * Hs + (size_t)(r0 + r) * Hs + j] = c;
    }
}

extern "C" void kernel_launch(void* const* d_in, const int* in_sizes, int n_in,
                              void* d_out, int out_size)
{
    const float* x    = (const float*)d_in[0];
    const float* h0   = (const float*)d_in[1];
    const float* c0   = (const float*)d_in[2];
    const float* Wih0 = (const float*)d_in[3];
    const float* Whh0 = (const float*)d_in[4];
    const float* bih0 = (const float*)d_in[5];
    const float* bhh0 = (const float*)d_in[6];
    const float* Wih1 = (const float*)d_in[7];
    const float* Whh1 = (const float*)d_in[8];
    const float* bih1 = (const float*)d_in[9];
    const float* bhh1 = (const float*)d_in[10];
    const float* Wh   = (const float*)d_in[11];
    const float* bh   = (const float*)d_in[12];
    float* out = (float*)d_out;

    dim3 pre_grid(SEQ / 64, Bt);
    xproj_kernel<<<pre_grid, 256>>>(x, Wih0, bih0, bhh0);
    lstm2_r8<<<Bt / 2, 512>>>(h0, c0, Whh0, Wih1, Whh1,
                              bih1, bhh1, Wh, bh, out);
}

// round 9
// speedup vs baseline: 1.7429x; 1.7429x over previous
#include <cuda_runtime.h>
#include <math.h>

#define Hs    64
#define SEQ   2048
#define Bt    256
#define IN    32
#define GATES 256   // 4*H

typedef unsigned long long u64;

__device__ float g_xproj[(size_t)SEQ * Bt * GATES];   // [t][row][g], bias0 folded

__device__ __forceinline__ u64 fma2(u64 a, u64 b, u64 c) {
    u64 d;
    asm("fma.rn.f32x2 %0, %1, %2, %3;" : "=l"(d) : "l"(a), "l"(b), "l"(c));
    return d;
}
__device__ __forceinline__ u64 pk(float a, float b) {
    u64 r;
    asm("mov.b64 %0, {%1, %2};" : "=l"(r) : "f"(a), "f"(b));
    return r;
}
__device__ __forceinline__ float hsum(u64 v) {
    float a, b;
    asm("mov.b64 {%0, %1}, %2;" : "=f"(a), "=f"(b) : "l"(v));
    return a + b;
}
__device__ __forceinline__ float ex2a(float x) {
    float y; asm("ex2.approx.f32 %0, %1;" : "=f"(y) : "f"(x)); return y;
}
__device__ __forceinline__ float rcpa(float x) {
    float y; asm("rcp.approx.f32 %0, %1;" : "=f"(y) : "f"(x)); return y;
}
__device__ __forceinline__ float sigf(float x) {
    return rcpa(1.0f + ex2a(-1.4426950408889634f * x));
}
__device__ __forceinline__ float tanhfa(float x) {
    return fmaf(2.0f, sigf(2.0f * x), -1.0f);
}

// ============================================================================
// Prepass (round-4 proven version, ~357us): xproj = Wih0·x + bih0 + bhh0
// 1 gate/thread, 32 weight regs -> high occupancy for this latency-bound pass.
// ============================================================================
__global__ void __launch_bounds__(256)
xproj_kernel(const float* __restrict__ x,
             const float* __restrict__ Wih0,
             const float* __restrict__ bih0,
             const float* __restrict__ bhh0)
{
    __shared__ float sx[64 * IN];
    const int g   = threadIdx.x;
    const int row = blockIdx.y;
    const int t0  = blockIdx.x * 64;

    const float* xs = x + ((size_t)row * SEQ + t0) * IN;
    for (int i = g; i < 64 * IN / 4; i += 256)
        ((float4*)sx)[i] = ((const float4*)xs)[i];

    u64 w[IN / 2];
    const u64* wp = (const u64*)(Wih0 + g * IN);
#pragma unroll
    for (int k = 0; k < IN / 2; k++) w[k] = wp[k];
    const u64 bp = pk(bih0[g] + bhh0[g], 0.0f);
    __syncthreads();

    for (int tt = 0; tt < 64; tt++) {
        const ulonglong2* xv = (const ulonglong2*)(sx + tt * IN);
        u64 a = bp;
#pragma unroll
        for (int k = 0; k < IN / 4; k++) {
            ulonglong2 v = xv[k];
            a = fma2(w[2 * k],     v.x, a);
            a = fma2(w[2 * k + 1], v.y, a);
        }
        g_xproj[((size_t)(t0 + tt) * Bt + row) * GATES + g] = hsum(a);
    }
}

// ============================================================================
// Main (round-7 proven version, 2286us): 128 CTAs x 512 threads.
// tid = g + half*256 (half K-split). Half-rows of Whh0/Wih1/Whh1 in regs.
// Layer-pipelined, deferred head reduce, reg-prefetched xproj, 2 barriers.
// ============================================================================
__global__ void __launch_bounds__(512, 1)
lstm2_r7(const float* __restrict__ h0g,
         const float* __restrict__ c0g,
         const float* __restrict__ Whh0,
         const float* __restrict__ Wih1,
         const float* __restrict__ Whh1,
         const float* __restrict__ bih1,
         const float* __restrict__ bhh1,
         const float* __restrict__ Wh,
         const float* __restrict__ bhp,
         float* __restrict__ out)
{
    __shared__ float sP[4 * 512];    // [layer*2+row][g*2+half]
    __shared__ float sH0[2 * Hs];    // [row][j]
    __shared__ float sH1[2 * Hs];
    __shared__ float sPr[8];         // [parity][4]

    const int tid  = threadIdx.x;
    const int g    = tid & 255;
    const int half = tid >> 8;
    const int r0   = blockIdx.x * 2;

    // register weights: half-rows (32 floats = 16 u64 each)
    u64 wh0[16], wx1[16], wh1[16];
    {
        const u64* p0 = (const u64*)(Whh0 + g * Hs + half * 32);
        const u64* p1 = (const u64*)(Wih1 + g * Hs + half * 32);
        const u64* p2 = (const u64*)(Whh1 + g * Hs + half * 32);
#pragma unroll
        for (int k = 0; k < 16; k++) { wh0[k] = p0[k]; wx1[k] = p1[k]; wh1[k] = p2[k]; }
    }
    const float b1  = bih1[g] + bhh1[g];
    const float bh0 = bhp[0];
    const float whj = Wh[tid & 63];      // used by L1 updaters only

    float c = 0.0f, hn_prev = 0.0f;
    if (tid < 128) {                     // L0 updaters (warps 0-3)
        int r = tid >> 6, j = tid & 63;
        sH0[r * 64 + j] = h0g[(size_t)(r0 + r) * Hs + j];
        c = c0g[(size_t)(r0 + r) * Hs + j];
    }
    if (tid >= 256 && tid < 384) {       // L1 updaters (warps 8-11)
        int ub = tid - 256, r = ub >> 6, j = ub & 63;
        sH1[r * 64 + j] = h0g[(size_t)Bt * Hs + (size_t)(r0 + r) * Hs + j];
        c = c0g[(size_t)Bt * Hs + (size_t)(r0 + r) * Hs + j];
    }
    // xproj(t=0) prefetched into regs (half-0 threads only)
    float xp0 = 0.f, xp1 = 0.f;
    if (half == 0) {
        xp0 = g_xproj[((size_t)0 * Bt + r0) * GATES + g];
        xp1 = g_xproj[((size_t)0 * Bt + r0 + 1) * GATES + g];
    }
    __syncthreads();

    for (int u = 0; u <= SEQ; u++) {
        // prefetch xproj(u+1)
        float xpn0 = 0.f, xpn1 = 0.f;
        if (half == 0 && u + 1 < SEQ) {
            xpn0 = g_xproj[((size_t)(u + 1) * Bt + r0) * GATES + g];
            xpn1 = g_xproj[((size_t)(u + 1) * Bt + r0 + 1) * GATES + g];
        }

        // deferred head reduce for t=u-2 (hn_prev from iter u-1's L1 update)
        if (tid >= 256 && tid < 384 && u >= 2) {
            float p = hn_prev * whj;
#pragma unroll
            for (int off = 16; off; off >>= 1)
                p += __shfl_down_sync(0xffffffffu, p, off);
            if ((tid & 31) == 0) sPr[(u & 1) * 4 + ((tid >> 5) - 8)] = p;
        }

        // ---------- phase 1: partial gates ----------
        {
            const ulonglong2* H0 = (const ulonglong2*)sH0;
            const ulonglong2* H1 = (const ulonglong2*)sH1;
            u64 a0, a1, q0, q1;
            if (half == 0) { a0 = pk(xp0, 0.f); a1 = pk(xp1, 0.f);
                             q0 = pk(b1, 0.f);  q1 = q0; }
            else           { a0 = 0ULL; a1 = 0ULL; q0 = 0ULL; q1 = 0ULL; }
#pragma unroll
            for (int k = 0; k < 8; k++) {      // h0(u-1) feeds Whh0 AND Wih1
                ulonglong2 v0 = H0[half * 8 + k];
                ulonglong2 v1 = H0[16 + half * 8 + k];
                a0 = fma2(wh0[2*k],   v0.x, a0);
                a0 = fma2(wh0[2*k+1], v0.y, a0);
                a1 = fma2(wh0[2*k],   v1.x, a1);
                a1 = fma2(wh0[2*k+1], v1.y, a1);
                q0 = fma2(wx1[2*k],   v0.x, q0);
                q0 = fma2(wx1[2*k+1], v0.y, q0);
                q1 = fma2(wx1[2*k],   v1.x, q1);
                q1 = fma2(wx1[2*k+1], v1.y, q1);
            }
            if (u < SEQ) {
                sP[g * 2 + half]       = hsum(a0);
                sP[512 + g * 2 + half] = hsum(a1);
            }
#pragma unroll
            for (int k = 0; k < 8; k++) {      // Whh1 over h1(u-2)
                ulonglong2 v0 = H1[half * 8 + k];
                ulonglong2 v1 = H1[16 + half * 8 + k];
                q0 = fma2(wh1[2*k],   v0.x, q0);
                q0 = fma2(wh1[2*k+1], v0.y, q0);
                q1 = fma2(wh1[2*k],   v1.x, q1);
                q1 = fma2(wh1[2*k+1], v1.y, q1);
            }
            if (u >= 1) {
                sP[1024 + g * 2 + half] = hsum(q0);
                sP[1536 + g * 2 + half] = hsum(q1);
            }
        }
        xp0 = xpn0; xp1 = xpn1;
        __syncthreads();

        // ---------- phase 2: combine + activate + update ----------
        if (tid < 128 && u < SEQ) {            // L0: time u
            int r = tid >> 6, j = tid & 63;
            const float2* p = (const float2*)(sP + r * 512);
            float2 vi = p[j], vf = p[64 + j], vg = p[128 + j], vo = p[192 + j];
            float si = sigf(vi.x + vi.y);
            float sf = sigf(vf.x + vf.y);
            float sg = tanhfa(vg.x + vg.y);
            float so = sigf(vo.x + vo.y);
            c = sf * c + si * sg;
            sH0[r * 64 + j] = so * tanhfa(c);
        }
        if (tid >= 256 && tid < 384 && u >= 1) {   // L1: time u-1
            int ub = tid - 256, r = ub >> 6, j = ub & 63;
            const float2* p = (const float2*)(sP + (2 + r) * 512);
            float2 vi = p[j], vf = p[64 + j], vg = p[128 + j], vo = p[192 + j];
            float si = sigf(vi.x + vi.y);
            float sf = sigf(vf.x + vf.y);
            float sg = tanhfa(vg.x + vg.y);
            float so = sigf(vo.x + vo.y);
            c = sf * c + si * sg;
            float hn = so * tanhfa(c);
            sH1[r * 64 + j] = hn;
            hn_prev = hn;                      // reduced at top of next iter
        }
        if (u >= 2 && (tid == 384 || tid == 385)) {  // head out, t=u-2
            int row = tid - 384;
            float v = sPr[(u & 1) * 4 + row * 2]
                    + sPr[(u & 1) * 4 + row * 2 + 1] + bh0;
            out[(size_t)(r0 + row) * SEQ + (u - 2)] = sigf(v);
        }
        __syncthreads();
    }

    // post-loop: reduce hn_prev (L1 t=SEQ-1) and emit last head sample
    if (tid >= 256 && tid < 384) {
        float p = hn_prev * whj;
#pragma unroll
        for (int off = 16; off; off >>= 1)
            p += __shfl_down_sync(0xffffffffu, p, off);
        if ((tid & 31) == 0) sPr[4 + ((tid >> 5) - 8)] = p;
    }
    __syncthreads();
    if (tid == 384 || tid == 385) {
        int row = tid - 384;
        float v = sPr[4 + row * 2] + sPr[4 + row * 2 + 1] + bh0;
        out[(size_t)(r0 + row) * SEQ + (SEQ - 1)] = sigf(v);
    }

    // final h, c
    const size_t hb = (size_t)Bt * SEQ;
    const size_t cb = hb + 2 * (size_t)Bt * Hs;
    if (tid < 128) {
        int r = tid >> 6, j = tid & 63;
        out[hb + (size_t)(r0 + r) * Hs + j] = sH0[r * 64 + j];
        out[cb + (size_t)(r0 + r) * Hs + j] = c;
    }
    if (tid >= 256 && tid < 384) {
        int ub = tid - 256, r = ub >> 6, j = ub & 63;
        out[hb + Bt * Hs + (size_t)(r0 + r) * Hs + j] = sH1[r * 64 + j];
        out[cb + Bt * Hs + (size_t)(r0 + r) * Hs + j] = c;
    }
}

extern "C" void kernel_launch(void* const* d_in, const int* in_sizes, int n_in,
                              void* d_out, int out_size)
{
    const float* x    = (const float*)d_in[0];
    const float* h0   = (const float*)d_in[1];
    const float* c0   = (const float*)d_in[2];
    const float* Wih0 = (const float*)d_in[3];
    const float* Whh0 = (const float*)d_in[4];
    const float* bih0 = (const float*)d_in[5];
    const float* bhh0 = (const float*)d_in[6];
    const float* Wih1 = (const float*)d_in[7];
    const float* Whh1 = (const float*)d_in[8];
    const float* bih1 = (const float*)d_in[9];
    const float* bhh1 = (const float*)d_in[10];
    const float* Wh   = (const float*)d_in[11];
    const float* bh   = (const float*)d_in[12];
    float* out = (float*)d_out;

    dim3 pre_grid(SEQ / 64, Bt);
    xproj_kernel<<<pre_grid, 256>>>(x, Wih0, bih0, bhh0);
    lstm2_r7<<<Bt / 2, 512>>>(h0, c0, Whh0, Wih1, Whh1,
                              bih1, bhh1, Wh, bh, out);
}